// round 4
// baseline (speedup 1.0000x reference)
#include <cuda_runtime.h>
#include <math.h>

#define Tt 64
#define NT 512
#define SMS 520
#define EPSF 1e-8f
#define HOUT 272   // padded head outputs: 198 write + 70 read + 4 pad

__device__ __align__(16) float g_Wh[256 * HOUT];

struct __align__(16) Smem {
    float Msm[64 * SMS];      // M rows 512..1023, column-major
    float wtmp[1024];
    float scratchH[2048];     // ctrl/head/passC partials
    float scratchX[256];      // head outs 256..271 partials (16 ksplits x 16)
    float scratchF[2560];     // final FC partials (40 splits x 64)
    float cr[320];            // [c(256), r(64)]
    float xb[Tt * 64];        // preloaded x for this batch
    float kw[64], kr[64], ev[64], av[64];
    float redA[16], redB[16], red2[8], sc[16];
    float bcs[256], bws[200], brs[72], bfs[64];
};

__device__ __forceinline__ float sigmoidf_(float x) { return 1.f / (1.f + __expf(-x)); }
__device__ __forceinline__ float softplusf_(float x) { return (x > 20.f) ? x : log1pf(expf(x)); }

__device__ __forceinline__ float bredsum(float v, float* red, int lane, int wid) {
    #pragma unroll
    for (int o = 16; o; o >>= 1) v += __shfl_xor_sync(0xffffffffu, v, o);
    if (lane == 0) red[wid] = v;
    __syncthreads();
    float4 a = ((const float4*)red)[0];
    float4 b = ((const float4*)red)[1];
    float4 c = ((const float4*)red)[2];
    float4 d = ((const float4*)red)[3];
    return ((a.x + a.y) + (a.z + a.w)) + ((b.x + b.y) + (b.z + b.w))
         + ((c.x + c.y) + (c.z + c.w)) + ((d.x + d.y) + (d.z + d.w));
}

__global__ void prep_kernel(const float* __restrict__ Ww, const float* __restrict__ Wr) {
    int j = blockIdx.x, t = threadIdx.x;
    float v = 0.f;
    if (t < 198) v = Ww[(size_t)j * 198 + t];
    else if (t < 268) v = Wr[(size_t)j * 70 + (t - 198)];
    g_Wh[(size_t)j * HOUT + t] = v;
}

__global__ __launch_bounds__(NT, 1)
void ntm_kernel(const float* __restrict__ x,
                const float* __restrict__ Wc, const float* __restrict__ bc,
                const float* __restrict__ br, const float* __restrict__ bw,
                const float* __restrict__ Wf, const float* __restrict__ bf,
                const float* __restrict__ r_bias, const float* __restrict__ w_bias,
                const float* __restrict__ M_bias, float* __restrict__ out) {
    extern __shared__ float smem_raw[];
    Smem& s = *reinterpret_cast<Smem*>(smem_raw);
    const int tid = threadIdx.x;
    const int lane = tid & 31, wid = tid >> 5;
    const int b = blockIdx.x;
    float Mreg[64];
    float q0 = 0.f, q1 = 0.f;       // sumsq of owned rows (register-carried)

    // ---- init ----
    {
        const float* Mb = M_bias + (size_t)tid * 64;
        #pragma unroll
        for (int j = 0; j < 64; ++j) { float v = Mb[j]; Mreg[j] = v; q0 += v * v; }
        const float* Mb2 = M_bias + (size_t)(512 + tid) * 64;
        #pragma unroll 8
        for (int j = 0; j < 64; ++j) { float v = Mb2[j]; s.Msm[j * SMS + tid] = v; q1 += v * v; }
    }
    float wr0 = w_bias[tid], wr1 = w_bias[512 + tid];   // read weights (register-carried)
    if (tid < 64) s.cr[256 + tid] = r_bias[tid];
    for (int i = tid; i < Tt * 64; i += NT) s.xb[i] = x[(size_t)b * Tt * 64 + i];
    if (tid < 256) s.bcs[tid] = bc[tid];
    if (tid < 198) s.bws[tid] = bw[tid];
    if (tid < 70)  s.brs[tid] = br[tid];
    if (tid < 64)  s.bfs[tid] = bf[tid];
    __syncthreads();

    for (int t = 0; t < Tt; ++t) {
        // ---- (a) controller GEMV: 64 groups(x4) x 8 splits(16K) ----
        {
            const int g = tid & 63, split = tid >> 6;
            const float* src = (split < 4) ? (s.xb + t * 64 + split * 16)
                                           : (s.cr + 256 + (split - 4) * 16);
            const float4* w = (const float4*)Wc + (size_t)(split * 16) * 64 + g;
            float4 acc = make_float4(0.f, 0.f, 0.f, 0.f);
            #pragma unroll
            for (int j = 0; j < 16; ++j) {
                float v = src[j]; float4 w4 = w[(size_t)j * 64];
                acc.x = fmaf(v, w4.x, acc.x); acc.y = fmaf(v, w4.y, acc.y);
                acc.z = fmaf(v, w4.z, acc.z); acc.w = fmaf(v, w4.w, acc.w);
            }
            *(float4*)(s.scratchH + split * 256 + 4 * g) = acc;
        }
        __syncthreads();                                    // A
        if (tid < 256) {
            float acc = s.bcs[tid];
            #pragma unroll
            for (int k = 0; k < 8; ++k) acc += s.scratchH[k * 256 + tid];
            s.cr[tid] = tanhf(acc);
        }
        __syncthreads();                                    // B

        // ---- (c) head GEMV (outs 0..255) + head extra (256..271) + FC c-part ----
        {
            const int g = tid & 63, split = tid >> 6;
            const float4* w = (const float4*)g_Wh + (size_t)(split * 32) * (HOUT / 4) + g;
            float4 acc = make_float4(0.f, 0.f, 0.f, 0.f);
            #pragma unroll
            for (int j = 0; j < 32; ++j) {
                float v = s.cr[split * 32 + j]; float4 w4 = w[(size_t)j * (HOUT / 4)];
                acc.x = fmaf(v, w4.x, acc.x); acc.y = fmaf(v, w4.y, acc.y);
                acc.z = fmaf(v, w4.z, acc.z); acc.w = fmaf(v, w4.w, acc.w);
            }
            *(float4*)(s.scratchH + split * 256 + 4 * g) = acc;

            const int g3 = tid & 15, sp3 = tid >> 4;
            const float4* wf = (const float4*)Wf + (size_t)(sp3 * 8) * 16 + g3;
            float4 af = make_float4(0.f, 0.f, 0.f, 0.f);
            #pragma unroll
            for (int jj = 0; jj < 8; ++jj) {
                float v = s.cr[sp3 * 8 + jj]; float4 w4 = wf[(size_t)jj * 16];
                af.x = fmaf(v, w4.x, af.x); af.y = fmaf(v, w4.y, af.y);
                af.z = fmaf(v, w4.z, af.z); af.w = fmaf(v, w4.w, af.w);
            }
            *(float4*)(s.scratchF + sp3 * 64 + 4 * g3) = af;

            if (tid >= 448) {   // head outs 256..271: 4 groups x 16 ksplits(16K)
                int e = tid - 448;
                int g2 = 64 + (e & 3), kk = e >> 2;
                const float4* w2 = (const float4*)g_Wh + (size_t)(kk * 16) * (HOUT / 4) + g2;
                float4 a2 = make_float4(0.f, 0.f, 0.f, 0.f);
                #pragma unroll
                for (int j = 0; j < 16; ++j) {
                    float v = s.cr[kk * 16 + j]; float4 w4 = w2[(size_t)j * (HOUT / 4)];
                    a2.x = fmaf(v, w4.x, a2.x); a2.y = fmaf(v, w4.y, a2.y);
                    a2.z = fmaf(v, w4.z, a2.z); a2.w = fmaf(v, w4.w, a2.w);
                }
                *(float4*)(s.scratchX + kk * 16 + 4 * (e & 3)) = a2;
            }
        }
        __syncthreads();                                    // C

        // ---- (d) head reduce + transforms + key-norm reduces (fused) ----
        {
            float hv = 0.f;
            if (tid < 256) {
                hv = (tid < 198) ? s.bws[tid] : s.brs[tid - 198];
                #pragma unroll
                for (int k = 0; k < 8; ++k) hv += s.scratchH[k * 256 + tid];
            } else if (tid < 268) {
                hv = s.brs[tid - 198];
                #pragma unroll
                for (int k = 0; k < 16; ++k) hv += s.scratchX[k * 16 + (tid - 256)];
            }
            float kv = 0.f;
            if (tid < 64 || (tid >= 198 && tid < 262)) kv = tanhf(hv);
            if (tid < 64) s.kw[tid] = kv;
            else if (tid < 70) {              // warp 2 lanes 0..5: write-head scalars
                const unsigned m6 = 0x3Fu;
                float a0 = __shfl_sync(m6, hv, 2);
                float a1 = __shfl_sync(m6, hv, 3);
                float a2 = __shfl_sync(m6, hv, 4);
                if (lane == 0) s.sc[0] = softplusf_(hv);
                else if (lane == 1) s.sc[1] = sigmoidf_(hv);
                else if (lane == 5) s.sc[5] = 1.f + softplusf_(hv);
                else {
                    float m = fmaxf(a0, fmaxf(a1, a2));
                    float e0 = __expf(a0 - m), e1 = __expf(a1 - m), e2 = __expf(a2 - m);
                    float z = e0 + e1 + e2;
                    float mine = (lane == 2) ? e0 : (lane == 3) ? e1 : e2;
                    s.sc[2 + (lane - 2)] = mine / z;
                }
            }
            else if (tid < 134) s.ev[tid - 70] = sigmoidf_(hv);
            else if (tid < 198) s.av[tid - 134] = tanhf(hv);
            else if (tid < 262) s.kr[tid - 198] = kv;
            else if (tid < 268) {             // warp 8 lanes 6..11: read-head scalars
                const unsigned m6 = 0xFC0u;
                float a0 = __shfl_sync(m6, hv, 8);
                float a1 = __shfl_sync(m6, hv, 9);
                float a2 = __shfl_sync(m6, hv, 10);
                if (lane == 6) s.sc[8] = softplusf_(hv);
                else if (lane == 7) s.sc[9] = sigmoidf_(hv);
                else if (lane == 11) s.sc[13] = 1.f + softplusf_(hv);
                else {
                    float m = fmaxf(a0, fmaxf(a1, a2));
                    float e0 = __expf(a0 - m), e1 = __expf(a1 - m), e2 = __expf(a2 - m);
                    float z = e0 + e1 + e2;
                    float mine = (lane == 8) ? e0 : (lane == 9) ? e1 : e2;
                    s.sc[10 + (lane - 8)] = mine / z;
                }
            }
            float q = kv * kv;
            if (wid < 2 || (wid >= 6 && wid <= 8)) {
                #pragma unroll
                for (int o = 16; o; o >>= 1) q += __shfl_xor_sync(0xffffffffu, q, o);
                if (lane == 0) s.red2[wid < 2 ? wid : wid - 4] = q;
            }
        }
        __syncthreads();                                    // D

        // ---- Pass A: dots with k_w (registers only) ----
        float d0 = 0.f, d1 = 0.f;
        #pragma unroll
        for (int j4 = 0; j4 < 16; ++j4) {
            float4 kk = *(const float4*)(s.kw + 4 * j4);
            d0 += Mreg[4*j4]*kk.x + Mreg[4*j4+1]*kk.y + Mreg[4*j4+2]*kk.z + Mreg[4*j4+3]*kk.w;
            d1 += s.Msm[(4*j4  )*SMS+tid]*kk.x + s.Msm[(4*j4+1)*SMS+tid]*kk.y
                + s.Msm[(4*j4+2)*SMS+tid]*kk.z + s.Msm[(4*j4+3)*SMS+tid]*kk.w;
        }

        // ---- write-head addressing (no max-sub; weights stay in regs) ----
        float w0, w1;
        {
            float knw = sqrtf(s.red2[0] + s.red2[1]);
            float beta = s.sc[0], gg = s.sc[1];
            float sh0 = s.sc[2], sh1 = s.sc[3], sh2 = s.sc[4], gamma = s.sc[5];
            float p0 = __expf(beta * d0 / (sqrtf(q0) * knw + EPSF));
            float p1 = __expf(beta * d1 / (sqrtf(q1) * knw + EPSF));
            float Z = bredsum(p0 + p1, s.redA, lane, wid);
            float inv = 1.f / Z;
            float wg0 = gg * p0 * inv + (1.f - gg) * wr0;
            float wg1 = gg * p1 * inv + (1.f - gg) * wr1;
            s.wtmp[tid] = wg0; s.wtmp[512 + tid] = wg1;
            __syncthreads();                                // G
            float ws0 = sh0*s.wtmp[(tid+1)&1023] + sh1*wg0 + sh2*s.wtmp[(tid-1)&1023];
            float ws1 = sh0*s.wtmp[(tid+513)&1023] + sh1*wg1 + sh2*s.wtmp[(tid+511)&1023];
            float wp0 = exp2f(gamma * __log2f(ws0 + EPSF));
            float wp1 = exp2f(gamma * __log2f(ws1 + EPSF));
            float S = bredsum(wp0 + wp1, s.redB, lane, wid);
            float invS = 1.f / S;
            w0 = wp0 * invS; w1 = wp1 * invS;
        }

        // ---- Pass B: erase/add + dots with k_r + new sumsq (no syncs) ----
        {
            float nd0 = 0.f, nq0 = 0.f, nd1 = 0.f, nq1 = 0.f;
            #pragma unroll
            for (int j4 = 0; j4 < 16; ++j4) {
                float4 kk = *(const float4*)(s.kr + 4 * j4);
                float4 ee = *(const float4*)(s.ev + 4 * j4);
                float4 aa = *(const float4*)(s.av + 4 * j4);
                #pragma unroll
                for (int e = 0; e < 4; ++e) {
                    int j = 4 * j4 + e;
                    float ev_ = (e==0)?ee.x:(e==1)?ee.y:(e==2)?ee.z:ee.w;
                    float av_ = (e==0)?aa.x:(e==1)?aa.y:(e==2)?aa.z:aa.w;
                    float kv_ = (e==0)?kk.x:(e==1)?kk.y:(e==2)?kk.z:kk.w;
                    float mr = Mreg[j];
                    mr = mr * (1.f - w0 * ev_) + w0 * av_;
                    Mreg[j] = mr;
                    nd0 = fmaf(mr, kv_, nd0); nq0 = fmaf(mr, mr, nq0);
                    float ms = s.Msm[j * SMS + tid];
                    ms = ms * (1.f - w1 * ev_) + w1 * av_;
                    s.Msm[j * SMS + tid] = ms;
                    nd1 = fmaf(ms, kv_, nd1); nq1 = fmaf(ms, ms, nq1);
                }
            }
            d0 = nd0; q0 = nq0; d1 = nd1; q1 = nq1;
        }

        // ---- read-head addressing ----
        {
            float knr = sqrtf(s.red2[2] + s.red2[3] + s.red2[4]);
            float beta = s.sc[8], gg = s.sc[9];
            float sh0 = s.sc[10], sh1 = s.sc[11], sh2 = s.sc[12], gamma = s.sc[13];
            float p0 = __expf(beta * d0 / (sqrtf(q0) * knr + EPSF));
            float p1 = __expf(beta * d1 / (sqrtf(q1) * knr + EPSF));
            float Z = bredsum(p0 + p1, s.redA, lane, wid);
            float inv = 1.f / Z;
            float wg0 = gg * p0 * inv + (1.f - gg) * w0;
            float wg1 = gg * p1 * inv + (1.f - gg) * w1;
            s.wtmp[tid] = wg0; s.wtmp[512 + tid] = wg1;
            __syncthreads();                                // J
            float ws0 = sh0*s.wtmp[(tid+1)&1023] + sh1*wg0 + sh2*s.wtmp[(tid-1)&1023];
            float ws1 = sh0*s.wtmp[(tid+513)&1023] + sh1*wg1 + sh2*s.wtmp[(tid+511)&1023];
            float wp0 = exp2f(gamma * __log2f(ws0 + EPSF));
            float wp1 = exp2f(gamma * __log2f(ws1 + EPSF));
            float S = bredsum(wp0 + wp1, s.redB, lane, wid);
            float invS = 1.f / S;
            wr0 = wp0 * invS; wr1 = wp1 * invS;
        }

        // ---- Pass C: r = sum_n w_r[n] M[n] (warp butterfly) ----
        {
            float A[32];
            bool up = (lane & 16);
            #pragma unroll
            for (int i = 0; i < 32; ++i) {
                float lo = wr0 * Mreg[i]      + wr1 * s.Msm[i * SMS + tid];
                float hi = wr0 * Mreg[i + 32] + wr1 * s.Msm[(i + 32) * SMS + tid];
                float keep = up ? hi : lo;
                float send = up ? lo : hi;
                A[i] = keep + __shfl_xor_sync(0xffffffffu, send, 16);
            }
            #pragma unroll
            for (int o = 8; o >= 1; o >>= 1) {
                int hl = o << 1;
                bool u2 = (lane & o);
                #pragma unroll
                for (int i = 0; i < 16; ++i) {
                    if (i < hl) {
                        float keep = u2 ? A[i + hl] : A[i];
                        float send = u2 ? A[i] : A[i + hl];
                        A[i] = keep + __shfl_xor_sync(0xffffffffu, send, o);
                    }
                }
            }
            s.scratchH[wid * 64 + 2 * lane]     = A[0];
            s.scratchH[wid * 64 + 2 * lane + 1] = A[1];
        }
        __syncthreads();                                    // L
        if (tid < 64) {
            float acc = 0.f;
            #pragma unroll
            for (int w = 0; w < 16; ++w) acc += s.scratchH[w * 64 + tid];
            s.cr[256 + tid] = acc;
        }
        __syncthreads();                                    // M

        // ---- FC r-part: 16 groups(x4) x 8 splits(8K) on tid<128 ----
        if (tid < 128) {
            const int g = tid & 15, sp = tid >> 4;
            const float4* w = (const float4*)Wf + (size_t)(256 + sp * 8) * 16 + g;
            float4 acc = make_float4(0.f, 0.f, 0.f, 0.f);
            #pragma unroll
            for (int jj = 0; jj < 8; ++jj) {
                float v = s.cr[256 + sp * 8 + jj]; float4 w4 = w[(size_t)jj * 16];
                acc.x = fmaf(v, w4.x, acc.x); acc.y = fmaf(v, w4.y, acc.y);
                acc.z = fmaf(v, w4.z, acc.z); acc.w = fmaf(v, w4.w, acc.w);
            }
            *(float4*)(s.scratchF + (32 + sp) * 64 + 4 * g) = acc;
        }
        __syncthreads();                                    // N
        if (tid < 64) {
            float acc = s.bfs[tid];
            #pragma unroll
            for (int k = 0; k < 40; ++k) acc += s.scratchF[k * 64 + tid];
            out[((size_t)b * Tt + t) * 64 + tid] = sigmoidf_(acc);
        }
        // no trailing sync needed (scratchF next written after 2 syncs)
    }
}

extern "C" void kernel_launch(void* const* d_in, const int* in_sizes, int n_in,
                              void* d_out, int out_size) {
    (void)in_sizes; (void)n_in; (void)out_size;
    prep_kernel<<<256, HOUT>>>((const float*)d_in[5], (const float*)d_in[3]);
    cudaFuncSetAttribute(ntm_kernel, cudaFuncAttributeMaxDynamicSharedMemorySize,
                         (int)sizeof(Smem));
    ntm_kernel<<<64, NT, sizeof(Smem)>>>(
        (const float*)d_in[0],   // x
        (const float*)d_in[1],   // Wc
        (const float*)d_in[2],   // bc
        (const float*)d_in[4],   // br
        (const float*)d_in[6],   // bw
        (const float*)d_in[7],   // Wf
        (const float*)d_in[8],   // bf
        (const float*)d_in[9],   // r_bias
        (const float*)d_in[10],  // w_bias
        (const float*)d_in[11],  // M_bias
        (float*)d_out);
}

// round 6
// speedup vs baseline: 1.2818x; 1.2818x over previous
#include <cuda_runtime.h>
#include <cstdint>
#include <math.h>

#define Tt 64
#define NT 512
#define EPSF 1e-8f

__device__ __forceinline__ float sigmoidf_(float x) { return 1.f / (1.f + __expf(-x)); }
__device__ __forceinline__ float softplusf_(float x) { return (x > 20.f) ? x : log1pf(expf(x)); }

__device__ __forceinline__ uint32_t s2u(const void* p) {
    uint32_t a;
    asm("{ .reg .u64 t; cvta.to.shared.u64 t, %1; cvt.u32.u64 %0, t; }" : "=r"(a) : "l"(p));
    return a;
}
__device__ __forceinline__ void st_peer(const void* lp, uint32_t peer, float v) {
    uint32_t la = s2u(lp), ra;
    asm("mapa.shared::cluster.u32 %0, %1, %2;" : "=r"(ra) : "r"(la), "r"(peer));
    asm volatile("st.shared::cluster.f32 [%0], %1;" :: "r"(ra), "f"(v));
}
#define CSYNC() do { \
    asm volatile("barrier.cluster.arrive.aligned;" ::: "memory"); \
    asm volatile("barrier.cluster.wait.aligned;" ::: "memory"); } while (0)

struct __align__(16) Smem {
    float Whs[256 * 136];     // head-weight slice (outs rank*136..+136)
    float Wcs[128 * 128];     // controller-weight slice (cols rank*128..+128)
    float scratch[2176];      // GEMV / Pass C partials
    float scratchF[768];      // FC partials (24 splits x 32)
    float cr[320];            // full [c(256), r(64)]
    float cat[128];
    float hraw[272];          // full raw head outs (exchanged)
    float wtmp[512];
    float haloW[2], haloR[2]; // shift halo (peer-pushed)
    float kw[64], kr[64], ev[64], av[64];
    float redA[16], redB[16], red2[8], sc[16];
    float mbox[4];            // Zw, Sw, Zr, Sr (peer partials)
    float rpart[64];          // peer's r partial
};

__device__ __forceinline__ float bredsum(float v, float* red, int lane, int wid) {
    #pragma unroll
    for (int o = 16; o; o >>= 1) v += __shfl_xor_sync(0xffffffffu, v, o);
    if (lane == 0) red[wid] = v;
    __syncthreads();
    float4 a = ((const float4*)red)[0];
    float4 b = ((const float4*)red)[1];
    float4 c = ((const float4*)red)[2];
    float4 d = ((const float4*)red)[3];
    return ((a.x + a.y) + (a.z + a.w)) + ((b.x + b.y) + (b.z + b.w))
         + ((c.x + c.y) + (c.z + c.w)) + ((d.x + d.y) + (d.z + d.w));
}

__global__ __launch_bounds__(NT, 1) __cluster_dims__(2, 1, 1)
void ntm_kernel(const float* __restrict__ x,
                const float* __restrict__ Wc, const float* __restrict__ bc,
                const float* __restrict__ Wr, const float* __restrict__ br,
                const float* __restrict__ Ww, const float* __restrict__ bw,
                const float* __restrict__ Wf, const float* __restrict__ bf,
                const float* __restrict__ r_bias, const float* __restrict__ w_bias,
                const float* __restrict__ M_bias, float* __restrict__ out) {
    extern __shared__ float smem_raw[];
    Smem& s = *reinterpret_cast<Smem*>(smem_raw);
    const int tid = threadIdx.x;
    const int lane = tid & 31, wid = tid >> 5;
    uint32_t rank;
    asm("mov.u32 %0, %%cluster_ctarank;" : "=r"(rank));
    const uint32_t peer = rank ^ 1u;
    const int b = blockIdx.x >> 1;
    const float4* Wf4 = (const float4*)Wf;
    const float4* Wcs4 = (const float4*)s.Wcs;
    const float4* Whs4 = (const float4*)s.Whs;

    float Mreg[64];
    float q, d;

    // ---- init: weight slices into SMEM ----
    for (int i = tid; i < 128 * 128; i += NT) {
        int j = i >> 7, c = i & 127;
        s.Wcs[i] = Wc[(size_t)j * 256 + rank * 128 + c];
    }
    for (int i = tid; i < 256 * 136; i += NT) {
        int j = i / 136, c = i - j * 136;
        int col = rank * 136 + c;
        float v = 0.f;
        if (col < 198) v = Ww[(size_t)j * 198 + col];
        else if (col < 268) v = Wr[(size_t)j * 70 + (col - 198)];
        s.Whs[i] = v;
    }
    // ---- init state: 1 row per thread ----
    {
        const int row = rank * 512 + tid;
        q = 0.f;
        const float* Mb = M_bias + (size_t)row * 64;
        #pragma unroll
        for (int j = 0; j < 64; ++j) { float v = Mb[j]; Mreg[j] = v; q += v * v; }
    }
    float wr = w_bias[rank * 512 + tid];
    if (tid < 64) s.cr[256 + tid] = r_bias[tid];
    float xreg = (tid < 64) ? x[(size_t)b * Tt * 64 + tid] : 0.f;
    __syncthreads();
    CSYNC();

    for (int t = 0; t < Tt; ++t) {
        // ---- cat = [x_t, r] ----
        if (tid < 64) s.cat[tid] = xreg;
        else if (tid < 128) s.cat[tid] = s.cr[256 + tid - 64];
        __syncthreads();
        if (tid < 64 && t + 1 < Tt)
            xreg = x[((size_t)b * Tt + t + 1) * 64 + tid];   // prefetch

        // ---- controller GEMV (our 128 cols): 32 groups x 16 splits(8K) ----
        {
            const int g = tid & 31, sp = tid >> 5;
            float4 acc = make_float4(0.f, 0.f, 0.f, 0.f);
            #pragma unroll
            for (int j = 0; j < 8; ++j) {
                float v = s.cat[sp * 8 + j];
                float4 w4 = Wcs4[(size_t)(sp * 8 + j) * 32 + g];
                acc.x = fmaf(v, w4.x, acc.x); acc.y = fmaf(v, w4.y, acc.y);
                acc.z = fmaf(v, w4.z, acc.z); acc.w = fmaf(v, w4.w, acc.w);
            }
            *(float4*)(s.scratch + sp * 128 + 4 * g) = acc;
        }
        __syncthreads();
        if (tid < 128) {
            float acc = bc[rank * 128 + tid];
            #pragma unroll
            for (int k = 0; k < 16; ++k) acc += s.scratch[k * 128 + tid];
            float cv = tanhf(acc);
            s.cr[rank * 128 + tid] = cv;
            st_peer(&s.cr[rank * 128 + tid], peer, cv);
        }
        CSYNC();                                            // 1: c full

        // ---- head GEMV (our 136 outs) + FC c-part (our 32 outs) ----
        {
            int g = tid % 34, sp = tid / 34;                // jobs 0..511
            float4 acc = make_float4(0.f, 0.f, 0.f, 0.f);
            #pragma unroll
            for (int j = 0; j < 16; ++j) {
                float v = s.cr[sp * 16 + j];
                float4 w4 = Whs4[(size_t)(sp * 16 + j) * 34 + g];
                acc.x = fmaf(v, w4.x, acc.x); acc.y = fmaf(v, w4.y, acc.y);
                acc.z = fmaf(v, w4.z, acc.z); acc.w = fmaf(v, w4.w, acc.w);
            }
            *(float4*)(s.scratch + sp * 136 + 4 * g) = acc;
            if (tid < 32) {                                 // jobs 512..543: sp=15, g=2+tid
                int g2 = 2 + tid;
                float4 a2 = make_float4(0.f, 0.f, 0.f, 0.f);
                #pragma unroll
                for (int j = 0; j < 16; ++j) {
                    float v = s.cr[15 * 16 + j];
                    float4 w4 = Whs4[(size_t)(15 * 16 + j) * 34 + g2];
                    a2.x = fmaf(v, w4.x, a2.x); a2.y = fmaf(v, w4.y, a2.y);
                    a2.z = fmaf(v, w4.z, a2.z); a2.w = fmaf(v, w4.w, a2.w);
                }
                *(float4*)(s.scratch + 15 * 136 + 4 * g2) = a2;
            }
            if (tid < 128) {                                // FC c-part: 8 groups x 16 splits(16K)
                int gf = tid & 7, spf = tid >> 3;
                float4 af = make_float4(0.f, 0.f, 0.f, 0.f);
                #pragma unroll
                for (int j = 0; j < 16; ++j) {
                    float v = s.cr[spf * 16 + j];
                    float4 w4 = Wf4[(size_t)(spf * 16 + j) * 16 + rank * 8 + gf];
                    af.x = fmaf(v, w4.x, af.x); af.y = fmaf(v, w4.y, af.y);
                    af.z = fmaf(v, w4.z, af.z); af.w = fmaf(v, w4.w, af.w);
                }
                *(float4*)(s.scratchF + spf * 32 + 4 * gf) = af;
            }
        }
        __syncthreads();
        if (tid < 136) {
            int og = rank * 136 + tid;
            float acc = (og < 198) ? bw[og] : ((og < 268) ? br[og - 198] : 0.f);
            #pragma unroll
            for (int k = 0; k < 16; ++k) acc += s.scratch[k * 136 + tid];
            s.hraw[og] = acc;
            st_peer(&s.hraw[og], peer, acc);
        }
        CSYNC();                                            // 2: raw head outs full

        // ---- transforms (both CTAs duplicate) ----
        {
            float hv = (tid < 268) ? s.hraw[tid] : 0.f;
            float kv = 0.f;
            if (tid < 64 || (tid >= 198 && tid < 262)) kv = tanhf(hv);
            if (tid < 64) s.kw[tid] = kv;
            else if (tid < 70) {
                const unsigned m6 = 0x3Fu;
                float a0 = __shfl_sync(m6, hv, 2);
                float a1 = __shfl_sync(m6, hv, 3);
                float a2 = __shfl_sync(m6, hv, 4);
                if (lane == 0) s.sc[0] = softplusf_(hv);
                else if (lane == 1) s.sc[1] = sigmoidf_(hv);
                else if (lane == 5) s.sc[5] = 1.f + softplusf_(hv);
                else {
                    float m = fmaxf(a0, fmaxf(a1, a2));
                    float e0 = __expf(a0 - m), e1 = __expf(a1 - m), e2 = __expf(a2 - m);
                    float z = e0 + e1 + e2;
                    float mine = (lane == 2) ? e0 : (lane == 3) ? e1 : e2;
                    s.sc[2 + (lane - 2)] = mine / z;
                }
            }
            else if (tid < 134) s.ev[tid - 70] = sigmoidf_(hv);
            else if (tid < 198) s.av[tid - 134] = tanhf(hv);
            else if (tid < 262) s.kr[tid - 198] = kv;
            else if (tid < 268) {
                const unsigned m6 = 0xFC0u;
                float a0 = __shfl_sync(m6, hv, 8);
                float a1 = __shfl_sync(m6, hv, 9);
                float a2 = __shfl_sync(m6, hv, 10);
                if (lane == 6) s.sc[8] = softplusf_(hv);
                else if (lane == 7) s.sc[9] = sigmoidf_(hv);
                else if (lane == 11) s.sc[13] = 1.f + softplusf_(hv);
                else {
                    float m = fmaxf(a0, fmaxf(a1, a2));
                    float e0 = __expf(a0 - m), e1 = __expf(a1 - m), e2 = __expf(a2 - m);
                    float z = e0 + e1 + e2;
                    float mine = (lane == 8) ? e0 : (lane == 9) ? e1 : e2;
                    s.sc[10 + (lane - 8)] = mine / z;
                }
            }
            float qq = kv * kv;
            if (wid < 2 || (wid >= 6 && wid <= 8)) {
                #pragma unroll
                for (int o = 16; o; o >>= 1) qq += __shfl_xor_sync(0xffffffffu, qq, o);
                if (lane == 0) s.red2[wid < 2 ? wid : wid - 4] = qq;
            }
        }
        __syncthreads();

        // ---- Pass A: d = dot(Mreg, kw) ----
        d = 0.f;
        #pragma unroll
        for (int j4 = 0; j4 < 16; ++j4) {
            float4 kk = *(const float4*)(s.kw + 4 * j4);
            d += Mreg[4*j4]*kk.x + Mreg[4*j4+1]*kk.y + Mreg[4*j4+2]*kk.z + Mreg[4*j4+3]*kk.w;
        }

        // ---- write-head addressing ----
        float w;
        {
            float knw = sqrtf(s.red2[0] + s.red2[1]);
            float beta = s.sc[0], gg = s.sc[1];
            float sh0 = s.sc[2], sh1 = s.sc[3], sh2 = s.sc[4], gamma = s.sc[5];
            float p = __expf(beta * d / (sqrtf(q) * knw + EPSF));
            float Zl = bredsum(p, s.redA, lane, wid);
            if (tid == 0) st_peer(&s.mbox[0], peer, Zl);
            CSYNC();                                        // 3
            float Z = Zl + s.mbox[0];
            float wg = gg * p / Z + (1.f - gg) * wr;
            s.wtmp[tid] = wg;
            if (tid == 0) st_peer(&s.haloW[1], peer, wg);
            if (tid == 511) st_peer(&s.haloW[0], peer, wg);
            CSYNC();                                        // 4
            float left  = tid ? s.wtmp[tid - 1] : s.haloW[0];
            float right = (tid < 511) ? s.wtmp[tid + 1] : s.haloW[1];
            float ws = sh0 * right + sh1 * wg + sh2 * left;
            float wp = exp2f(gamma * __log2f(ws + EPSF));
            float Sl = bredsum(wp, s.redB, lane, wid);
            if (tid == 0) st_peer(&s.mbox[1], peer, Sl);
            CSYNC();                                        // 5
            w = wp / (Sl + s.mbox[1]);
        }

        // ---- Pass B: pure-register erase/add + dot(M',kr) + sumsq ----
        {
            float nd = 0.f, nq = 0.f;
            #pragma unroll
            for (int j4 = 0; j4 < 16; ++j4) {
                float4 kk = *(const float4*)(s.kr + 4 * j4);
                float4 ee = *(const float4*)(s.ev + 4 * j4);
                float4 aa = *(const float4*)(s.av + 4 * j4);
                #pragma unroll
                for (int e = 0; e < 4; ++e) {
                    int j = 4 * j4 + e;
                    float ev_ = (e==0)?ee.x:(e==1)?ee.y:(e==2)?ee.z:ee.w;
                    float av_ = (e==0)?aa.x:(e==1)?aa.y:(e==2)?aa.z:aa.w;
                    float kv_ = (e==0)?kk.x:(e==1)?kk.y:(e==2)?kk.z:kk.w;
                    float mr = Mreg[j];
                    mr = mr * (1.f - w * ev_) + w * av_;
                    Mreg[j] = mr;
                    nd = fmaf(mr, kv_, nd); nq = fmaf(mr, mr, nq);
                }
            }
            d = nd; q = nq;
        }

        // ---- read-head addressing ----
        {
            float knr = sqrtf(s.red2[2] + s.red2[3] + s.red2[4]);
            float beta = s.sc[8], gg = s.sc[9];
            float sh0 = s.sc[10], sh1 = s.sc[11], sh2 = s.sc[12], gamma = s.sc[13];
            float p = __expf(beta * d / (sqrtf(q) * knr + EPSF));
            float Zl = bredsum(p, s.redA, lane, wid);
            if (tid == 0) st_peer(&s.mbox[2], peer, Zl);
            CSYNC();                                        // 6
            float Z = Zl + s.mbox[2];
            float wg = gg * p / Z + (1.f - gg) * w;
            s.wtmp[tid] = wg;
            if (tid == 0) st_peer(&s.haloR[1], peer, wg);
            if (tid == 511) st_peer(&s.haloR[0], peer, wg);
            CSYNC();                                        // 7
            float left  = tid ? s.wtmp[tid - 1] : s.haloR[0];
            float right = (tid < 511) ? s.wtmp[tid + 1] : s.haloR[1];
            float ws = sh0 * right + sh1 * wg + sh2 * left;
            float wp = exp2f(gamma * __log2f(ws + EPSF));
            float Sl = bredsum(wp, s.redB, lane, wid);
            if (tid == 0) st_peer(&s.mbox[3], peer, Sl);
            CSYNC();                                        // 8
            wr = wp / (Sl + s.mbox[3]);
        }

        // ---- Pass C: local r partial via warp butterfly ----
        {
            float A[32];
            bool up = (lane & 16);
            #pragma unroll
            for (int i = 0; i < 32; ++i) {
                float lo = wr * Mreg[i];
                float hi = wr * Mreg[i + 32];
                float keep = up ? hi : lo;
                float send = up ? lo : hi;
                A[i] = keep + __shfl_xor_sync(0xffffffffu, send, 16);
            }
            #pragma unroll
            for (int o = 8; o >= 1; o >>= 1) {
                int hl = o << 1;
                bool u2 = (lane & o);
                #pragma unroll
                for (int i = 0; i < 16; ++i) {
                    if (i < hl) {
                        float keep = u2 ? A[i + hl] : A[i];
                        float send = u2 ? A[i] : A[i + hl];
                        A[i] = keep + __shfl_xor_sync(0xffffffffu, send, o);
                    }
                }
            }
            s.scratch[wid * 64 + 2 * lane]     = A[0];
            s.scratch[wid * 64 + 2 * lane + 1] = A[1];
        }
        __syncthreads();
        float rl = 0.f;
        if (tid < 64) {
            #pragma unroll
            for (int k = 0; k < 16; ++k) rl += s.scratch[k * 64 + tid];
            st_peer(&s.rpart[tid], peer, rl);
        }
        CSYNC();                                            // 9
        if (tid < 64) s.cr[256 + tid] = rl + s.rpart[tid];
        __syncthreads();

        // ---- FC r-part (our 32 outs): 8 groups x 8 splits(8K) ----
        if (tid < 64) {
            int gf = tid & 7, spf = tid >> 3;
            float4 acc = make_float4(0.f, 0.f, 0.f, 0.f);
            #pragma unroll
            for (int j = 0; j < 8; ++j) {
                float v = s.cr[256 + spf * 8 + j];
                float4 w4 = Wf4[(size_t)(256 + spf * 8 + j) * 16 + rank * 8 + gf];
                acc.x = fmaf(v, w4.x, acc.x); acc.y = fmaf(v, w4.y, acc.y);
                acc.z = fmaf(v, w4.z, acc.z); acc.w = fmaf(v, w4.w, acc.w);
            }
            *(float4*)(s.scratchF + (16 + spf) * 32 + 4 * gf) = acc;
        }
        __syncthreads();
        if (tid < 32) {
            int o = rank * 32 + tid;
            float acc = bf[o];
            #pragma unroll
            for (int k = 0; k < 24; ++k) acc += s.scratchF[k * 32 + tid];
            out[((size_t)b * Tt + t) * 64 + o] = sigmoidf_(acc);
        }
    }
    CSYNC();   // no CTA exits while peer may still push
}

extern "C" void kernel_launch(void* const* d_in, const int* in_sizes, int n_in,
                              void* d_out, int out_size) {
    (void)in_sizes; (void)n_in; (void)out_size;
    cudaFuncSetAttribute(ntm_kernel, cudaFuncAttributeMaxDynamicSharedMemorySize,
                         (int)sizeof(Smem));
    ntm_kernel<<<128, NT, sizeof(Smem)>>>(
        (const float*)d_in[0],   // x
        (const float*)d_in[1],   // Wc
        (const float*)d_in[2],   // bc
        (const float*)d_in[3],   // Wr
        (const float*)d_in[4],   // br
        (const float*)d_in[5],   // Ww
        (const float*)d_in[6],   // bw
        (const float*)d_in[7],   // Wf
        (const float*)d_in[8],   // bf
        (const float*)d_in[9],   // r_bias
        (const float*)d_in[10],  // w_bias
        (const float*)d_in[11],  // M_bias
        (float*)d_out);
}

// round 7
// speedup vs baseline: 1.4150x; 1.1039x over previous
#include <cuda_runtime.h>
#include <cstdint>
#include <math.h>

#define Tt 64
#define NT 512
#define EPSF 1e-8f

__device__ __forceinline__ float sigmoidf_(float x) { return 1.f / (1.f + __expf(-x)); }
__device__ __forceinline__ float softplusf_(float x) { return (x > 20.f) ? x : log1pf(expf(x)); }

__device__ __forceinline__ uint32_t s2u(const void* p) {
    uint32_t a;
    asm("{ .reg .u64 t; cvta.to.shared.u64 t, %1; cvt.u32.u64 %0, t; }" : "=r"(a) : "l"(p));
    return a;
}
__device__ __forceinline__ void st_peer(const void* lp, uint32_t peer, float v) {
    uint32_t la = s2u(lp), ra;
    asm("mapa.shared::cluster.u32 %0, %1, %2;" : "=r"(ra) : "r"(la), "r"(peer));
    asm volatile("st.shared::cluster.f32 [%0], %1;" :: "r"(ra), "f"(v));
}
#define CSYNC() do { \
    asm volatile("barrier.cluster.arrive.aligned;" ::: "memory"); \
    asm volatile("barrier.cluster.wait.aligned;" ::: "memory"); } while (0)

struct __align__(16) Smem {
    float Whs[128 * 272];     // head weights: our K-half x all 272 outs (139 KB)
    float Wcs[128 * 128];     // controller: full cat-K x our 128 cols (64 KB)
    float scratchU[2176];     // union: ctrl partials (16x128) / head partials (8x272) / passC (16x64)
    float scratchF[768];      // FC partials: c-part 8x64 | r-part 8x32
    float chalf[128];         // our c half
    float rv[64];             // full read vector
    float cat[128];           // [x_t, r]
    float hl[272], hp[272];   // head partials: local, peer
    float fcl[64], fcp[2][64];// FC c-part: local, peer (parity-buffered)
    float wtmp[512];
    float kw[64], kr[64], ev[64], av[64];
    float redA[32], redB[32]; // 16 local + 16 peer warp partials
    float red2[8], sc[16];
    float haloWp[2], haloWv[2], haloRp[2], haloRv[2];
    float rpart[64];
    float bws[200], brs[72], bfs[64], bcc[128];
};

__global__ __launch_bounds__(NT, 1) __cluster_dims__(2, 1, 1)
void ntm_kernel(const float* __restrict__ x,
                const float* __restrict__ Wc, const float* __restrict__ bc,
                const float* __restrict__ Wr, const float* __restrict__ br,
                const float* __restrict__ Ww, const float* __restrict__ bw,
                const float* __restrict__ Wf, const float* __restrict__ bf,
                const float* __restrict__ r_bias, const float* __restrict__ w_bias,
                const float* __restrict__ M_bias, float* __restrict__ out) {
    extern __shared__ float smem_raw[];
    Smem& s = *reinterpret_cast<Smem*>(smem_raw);
    const int tid = threadIdx.x;
    const int lane = tid & 31, wid = tid >> 5;
    uint32_t rank;
    asm("mov.u32 %0, %%cluster_ctarank;" : "=r"(rank));
    const uint32_t peer = rank ^ 1u;
    const int b = blockIdx.x >> 1;
    const float4* Wf4  = (const float4*)Wf;
    const float4* Wcs4 = (const float4*)s.Wcs;
    const float4* Whs4 = (const float4*)s.Whs;

    float Mreg[64];
    float q, d;

    // ---- init: weight slices ----
    for (int i = tid; i < 128 * 128; i += NT) {       // Wcs: full K x our cols
        int j = i >> 7, c = i & 127;
        s.Wcs[i] = Wc[(size_t)j * 256 + rank * 128 + c];
    }
    for (int i = tid; i < 128 * 272; i += NT) {       // Whs: our K-half x all outs
        int j = i / 272, col = i - j * 272;
        int gk = rank * 128 + j;
        float v = 0.f;
        if (col < 198) v = Ww[(size_t)gk * 198 + col];
        else if (col < 268) v = Wr[(size_t)gk * 70 + (col - 198)];
        s.Whs[i] = v;
    }
    {
        const int row = rank * 512 + tid;
        q = 0.f;
        const float* Mb = M_bias + (size_t)row * 64;
        #pragma unroll
        for (int j = 0; j < 64; ++j) { float v = Mb[j]; Mreg[j] = v; q += v * v; }
    }
    float wr = w_bias[rank * 512 + tid];
    if (tid < 64)  s.rv[tid] = r_bias[tid];
    if (tid < 198) s.bws[tid] = bw[tid];
    if (tid < 70)  s.brs[tid] = br[tid];
    if (tid < 64)  s.bfs[tid] = bf[tid];
    if (tid < 128) s.bcc[tid] = bc[rank * 128 + tid];
    float xreg = (tid < 64) ? x[(size_t)b * Tt * 64 + tid] : 0.f;
    __syncthreads();
    CSYNC();

    for (int t = 0; t < Tt; ++t) {
        const int par = t & 1;
        // ---- cat = [x_t, r] (local) ----
        if (tid < 64) s.cat[tid] = xreg;
        else if (tid < 128) s.cat[tid] = s.rv[tid - 64];
        __syncthreads();                                // S1
        if (tid < 64 && t + 1 < Tt)
            xreg = x[((size_t)b * Tt + t + 1) * 64 + tid];

        // ---- controller GEMV (our 128 cols, full cat-K): 32 grp x 16 sp(8K) ----
        {
            const int g = tid & 31, sp = tid >> 5;
            float4 acc = make_float4(0.f, 0.f, 0.f, 0.f);
            #pragma unroll
            for (int j = 0; j < 8; ++j) {
                float v = s.cat[sp * 8 + j];
                float4 w4 = Wcs4[(size_t)(sp * 8 + j) * 32 + g];
                acc.x = fmaf(v, w4.x, acc.x); acc.y = fmaf(v, w4.y, acc.y);
                acc.z = fmaf(v, w4.z, acc.z); acc.w = fmaf(v, w4.w, acc.w);
            }
            *(float4*)(s.scratchU + sp * 128 + 4 * g) = acc;
        }
        __syncthreads();                                // S2
        if (tid < 128) {
            float acc = s.bcc[tid];
            #pragma unroll
            for (int k = 0; k < 16; ++k) acc += s.scratchU[k * 128 + tid];
            s.chalf[tid] = tanhf(acc);
        }
        __syncthreads();                                // S3

        // ---- head GEMV partials (ALL 272 outs over our K-half) + FC c-part ----
        {
            int g = tid % 68, sp = tid / 68;            // jobs 0..511
            float4 acc = make_float4(0.f, 0.f, 0.f, 0.f);
            #pragma unroll
            for (int j = 0; j < 16; ++j) {
                float v = s.chalf[sp * 16 + j];
                float4 w4 = Whs4[(size_t)(sp * 16 + j) * 68 + g];
                acc.x = fmaf(v, w4.x, acc.x); acc.y = fmaf(v, w4.y, acc.y);
                acc.z = fmaf(v, w4.z, acc.z); acc.w = fmaf(v, w4.w, acc.w);
            }
            *(float4*)(s.scratchU + sp * 272 + 4 * g) = acc;
            if (tid < 32) {                             // extra jobs: sp=7, g=36..67
                int g2 = 36 + tid;
                float4 a2 = make_float4(0.f, 0.f, 0.f, 0.f);
                #pragma unroll
                for (int j = 0; j < 16; ++j) {
                    float v = s.chalf[7 * 16 + j];
                    float4 w4 = Whs4[(size_t)(7 * 16 + j) * 68 + g2];
                    a2.x = fmaf(v, w4.x, a2.x); a2.y = fmaf(v, w4.y, a2.y);
                    a2.z = fmaf(v, w4.z, a2.z); a2.w = fmaf(v, w4.w, a2.w);
                }
                *(float4*)(s.scratchU + 7 * 272 + 4 * g2) = a2;
            }
            if (tid >= 384) {                           // FC c-part: 16 grp x 8 sp(16K)
                int ft = tid - 384;
                int gf = ft & 15, spf = ft >> 4;
                float4 af = make_float4(0.f, 0.f, 0.f, 0.f);
                #pragma unroll
                for (int j = 0; j < 16; ++j) {
                    float v = s.chalf[spf * 16 + j];
                    float4 w4 = Wf4[(size_t)(rank * 128 + spf * 16 + j) * 16 + gf];
                    af.x = fmaf(v, w4.x, af.x); af.y = fmaf(v, w4.y, af.y);
                    af.z = fmaf(v, w4.z, af.z); af.w = fmaf(v, w4.w, af.w);
                }
                *(float4*)(s.scratchF + spf * 64 + 4 * gf) = af;
            }
        }
        __syncthreads();                                // S4
        if (tid < 272) {
            float acc = 0.f;
            #pragma unroll
            for (int k = 0; k < 8; ++k) acc += s.scratchU[k * 272 + tid];
            s.hl[tid] = acc;
            st_peer(&s.hp[tid], peer, acc);
        } else if (tid < 336) {
            int ft = tid - 272;
            float acc = 0.f;
            #pragma unroll
            for (int k = 0; k < 8; ++k) acc += s.scratchF[k * 64 + ft];
            s.fcl[ft] = acc;
            st_peer(&s.fcp[par][ft], peer, acc);
        }
        CSYNC();                                        // C1: head+fc partials

        // ---- transforms (duplicated in both CTAs) ----
        {
            float hv = 0.f;
            if (tid < 268)
                hv = s.hl[tid] + s.hp[tid] + ((tid < 198) ? s.bws[tid] : s.brs[tid - 198]);
            float kv = 0.f;
            if (tid < 64 || (tid >= 198 && tid < 262)) kv = tanhf(hv);
            if (tid < 64) s.kw[tid] = kv;
            else if (tid < 70) {
                const unsigned m6 = 0x3Fu;
                float a0 = __shfl_sync(m6, hv, 2);
                float a1 = __shfl_sync(m6, hv, 3);
                float a2 = __shfl_sync(m6, hv, 4);
                if (lane == 0) s.sc[0] = softplusf_(hv);
                else if (lane == 1) s.sc[1] = sigmoidf_(hv);
                else if (lane == 5) s.sc[5] = 1.f + softplusf_(hv);
                else {
                    float m = fmaxf(a0, fmaxf(a1, a2));
                    float e0 = __expf(a0 - m), e1 = __expf(a1 - m), e2 = __expf(a2 - m);
                    float z = e0 + e1 + e2;
                    float mine = (lane == 2) ? e0 : (lane == 3) ? e1 : e2;
                    s.sc[2 + (lane - 2)] = mine / z;
                }
            }
            else if (tid < 134) s.ev[tid - 70] = sigmoidf_(hv);
            else if (tid < 198) s.av[tid - 134] = tanhf(hv);
            else if (tid < 262) s.kr[tid - 198] = kv;
            else if (tid < 268) {
                const unsigned m6 = 0xFC0u;
                float a0 = __shfl_sync(m6, hv, 8);
                float a1 = __shfl_sync(m6, hv, 9);
                float a2 = __shfl_sync(m6, hv, 10);
                if (lane == 6) s.sc[8] = softplusf_(hv);
                else if (lane == 7) s.sc[9] = sigmoidf_(hv);
                else if (lane == 11) s.sc[13] = 1.f + softplusf_(hv);
                else {
                    float m = fmaxf(a0, fmaxf(a1, a2));
                    float e0 = __expf(a0 - m), e1 = __expf(a1 - m), e2 = __expf(a2 - m);
                    float z = e0 + e1 + e2;
                    float mine = (lane == 8) ? e0 : (lane == 9) ? e1 : e2;
                    s.sc[10 + (lane - 8)] = mine / z;
                }
            }
            float qq = kv * kv;
            if (wid < 2 || (wid >= 6 && wid <= 8)) {
                #pragma unroll
                for (int o = 16; o; o >>= 1) qq += __shfl_xor_sync(0xffffffffu, qq, o);
                if (lane == 0) s.red2[wid < 2 ? wid : wid - 4] = qq;
            }
        }
        __syncthreads();                                // S5

        // ---- Pass A: d = dot(Mreg, kw) ----
        d = 0.f;
        #pragma unroll
        for (int j4 = 0; j4 < 16; ++j4) {
            float4 kk = *(const float4*)(s.kw + 4 * j4);
            d += Mreg[4*j4]*kk.x + Mreg[4*j4+1]*kk.y + Mreg[4*j4+2]*kk.z + Mreg[4*j4+3]*kk.w;
        }

        // ---- write-head addressing ----
        float w;
        {
            float knw = sqrtf(s.red2[0] + s.red2[1]);
            float beta = s.sc[0], gg = s.sc[1];
            float sh0 = s.sc[2], sh1 = s.sc[3], sh2 = s.sc[4], gamma = s.sc[5];
            float p = __expf(beta * d / (sqrtf(q) * knw + EPSF));
            float pw = p;
            #pragma unroll
            for (int o = 16; o; o >>= 1) pw += __shfl_xor_sync(0xffffffffu, pw, o);
            if (lane == 0) { s.redA[wid] = pw; st_peer(&s.redA[16 + wid], peer, pw); }
            if (tid == 511) { st_peer(&s.haloWp[0], peer, p); st_peer(&s.haloWv[0], peer, wr); }
            if (tid == 0)   { st_peer(&s.haloWp[1], peer, p); st_peer(&s.haloWv[1], peer, wr); }
            CSYNC();                                    // C2: Z partials + halo raw
            float Z = 0.f;
            #pragma unroll
            for (int k = 0; k < 8; ++k) {
                float4 v4 = ((const float4*)s.redA)[k];
                Z += (v4.x + v4.y) + (v4.z + v4.w);
            }
            float invZ = 1.f / Z;
            float wg = gg * p * invZ + (1.f - gg) * wr;
            s.wtmp[tid] = wg;
            __syncthreads();                            // S6
            float h0 = gg * s.haloWp[0] * invZ + (1.f - gg) * s.haloWv[0];
            float h1 = gg * s.haloWp[1] * invZ + (1.f - gg) * s.haloWv[1];
            float left  = tid ? s.wtmp[tid - 1] : h0;
            float right = (tid < 511) ? s.wtmp[tid + 1] : h1;
            float ws = sh0 * right + sh1 * wg + sh2 * left;
            float wp = exp2f(gamma * __log2f(ws + EPSF));
            float sw = wp;
            #pragma unroll
            for (int o = 16; o; o >>= 1) sw += __shfl_xor_sync(0xffffffffu, sw, o);
            if (lane == 0) { s.redB[wid] = sw; st_peer(&s.redB[16 + wid], peer, sw); }
            CSYNC();                                    // C3: S partials
            float S = 0.f;
            #pragma unroll
            for (int k = 0; k < 8; ++k) {
                float4 v4 = ((const float4*)s.redB)[k];
                S += (v4.x + v4.y) + (v4.z + v4.w);
            }
            w = wp / S;
        }

        // ---- Pass B: register erase/add + dot(M',kr) + sumsq ----
        {
            float nd = 0.f, nq = 0.f;
            #pragma unroll
            for (int j4 = 0; j4 < 16; ++j4) {
                float4 kk = *(const float4*)(s.kr + 4 * j4);
                float4 ee = *(const float4*)(s.ev + 4 * j4);
                float4 aa = *(const float4*)(s.av + 4 * j4);
                #pragma unroll
                for (int e = 0; e < 4; ++e) {
                    int j = 4 * j4 + e;
                    float ev_ = (e==0)?ee.x:(e==1)?ee.y:(e==2)?ee.z:ee.w;
                    float av_ = (e==0)?aa.x:(e==1)?aa.y:(e==2)?aa.z:aa.w;
                    float kv_ = (e==0)?kk.x:(e==1)?kk.y:(e==2)?kk.z:kk.w;
                    float mr = Mreg[j];
                    mr = mr * (1.f - w * ev_) + w * av_;
                    Mreg[j] = mr;
                    nd = fmaf(mr, kv_, nd); nq = fmaf(mr, mr, nq);
                }
            }
            d = nd; q = nq;
        }

        // ---- read-head addressing ----
        {
            float knr = sqrtf(s.red2[2] + s.red2[3] + s.red2[4]);
            float beta = s.sc[8], gg = s.sc[9];
            float sh0 = s.sc[10], sh1 = s.sc[11], sh2 = s.sc[12], gamma = s.sc[13];
            float p = __expf(beta * d / (sqrtf(q) * knr + EPSF));
            float pw = p;
            #pragma unroll
            for (int o = 16; o; o >>= 1) pw += __shfl_xor_sync(0xffffffffu, pw, o);
            if (lane == 0) { s.redA[wid] = pw; st_peer(&s.redA[16 + wid], peer, pw); }
            if (tid == 511) { st_peer(&s.haloRp[0], peer, p); st_peer(&s.haloRv[0], peer, w); }
            if (tid == 0)   { st_peer(&s.haloRp[1], peer, p); st_peer(&s.haloRv[1], peer, w); }
            CSYNC();                                    // C4
            float Z = 0.f;
            #pragma unroll
            for (int k = 0; k < 8; ++k) {
                float4 v4 = ((const float4*)s.redA)[k];
                Z += (v4.x + v4.y) + (v4.z + v4.w);
            }
            float invZ = 1.f / Z;
            float wg = gg * p * invZ + (1.f - gg) * w;
            s.wtmp[tid] = wg;
            __syncthreads();                            // S7
            float h0 = gg * s.haloRp[0] * invZ + (1.f - gg) * s.haloRv[0];
            float h1 = gg * s.haloRp[1] * invZ + (1.f - gg) * s.haloRv[1];
            float left  = tid ? s.wtmp[tid - 1] : h0;
            float right = (tid < 511) ? s.wtmp[tid + 1] : h1;
            float ws = sh0 * right + sh1 * wg + sh2 * left;
            float wp = exp2f(gamma * __log2f(ws + EPSF));
            float sw = wp;
            #pragma unroll
            for (int o = 16; o; o >>= 1) sw += __shfl_xor_sync(0xffffffffu, sw, o);
            if (lane == 0) { s.redB[wid] = sw; st_peer(&s.redB[16 + wid], peer, sw); }
            CSYNC();                                    // C5
            float S = 0.f;
            #pragma unroll
            for (int k = 0; k < 8; ++k) {
                float4 v4 = ((const float4*)s.redB)[k];
                S += (v4.x + v4.y) + (v4.z + v4.w);
            }
            wr = wp / S;
        }

        // ---- Pass C: local r partial (warp butterfly) ----
        {
            float A[32];
            bool up = (lane & 16);
            #pragma unroll
            for (int i = 0; i < 32; ++i) {
                float lo = wr * Mreg[i];
                float hi = wr * Mreg[i + 32];
                float keep = up ? hi : lo;
                float send = up ? lo : hi;
                A[i] = keep + __shfl_xor_sync(0xffffffffu, send, 16);
            }
            #pragma unroll
            for (int o = 8; o >= 1; o >>= 1) {
                int hl2 = o << 1;
                bool u2 = (lane & o);
                #pragma unroll
                for (int i = 0; i < 16; ++i) {
                    if (i < hl2) {
                        float keep = u2 ? A[i + hl2] : A[i];
                        float send = u2 ? A[i] : A[i + hl2];
                        A[i] = keep + __shfl_xor_sync(0xffffffffu, send, o);
                    }
                }
            }
            s.scratchU[wid * 64 + 2 * lane]     = A[0];
            s.scratchU[wid * 64 + 2 * lane + 1] = A[1];
        }
        __syncthreads();                                // S8
        float rl = 0.f;
        if (tid < 64) {
            #pragma unroll
            for (int k = 0; k < 16; ++k) rl += s.scratchU[k * 64 + tid];
            st_peer(&s.rpart[tid], peer, rl);
        }
        CSYNC();                                        // C6: r partials
        if (tid < 64) s.rv[tid] = rl + s.rpart[tid];
        __syncthreads();                                // S9

        // ---- FC r-part (our 32 outs): 8 grp x 8 sp(8K) ----
        if (tid < 64) {
            int gf = tid & 7, spf = tid >> 3;
            float4 acc = make_float4(0.f, 0.f, 0.f, 0.f);
            #pragma unroll
            for (int j = 0; j < 8; ++j) {
                float v = s.rv[spf * 8 + j];
                float4 w4 = Wf4[(size_t)(256 + spf * 8 + j) * 16 + rank * 8 + gf];
                acc.x = fmaf(v, w4.x, acc.x); acc.y = fmaf(v, w4.y, acc.y);
                acc.z = fmaf(v, w4.z, acc.z); acc.w = fmaf(v, w4.w, acc.w);
            }
            *(float4*)(s.scratchF + 512 + spf * 32 + 4 * gf) = acc;
        }
        __syncthreads();                                // S10
        if (tid < 32) {
            int o = rank * 32 + tid;
            float acc = s.bfs[o] + s.fcl[o] + s.fcp[par][o];
            #pragma unroll
            for (int k = 0; k < 8; ++k) acc += s.scratchF[512 + k * 32 + tid];
            out[((size_t)b * Tt + t) * 64 + o] = sigmoidf_(acc);
        }
    }
    CSYNC();
}

extern "C" void kernel_launch(void* const* d_in, const int* in_sizes, int n_in,
                              void* d_out, int out_size) {
    (void)in_sizes; (void)n_in; (void)out_size;
    cudaFuncSetAttribute(ntm_kernel, cudaFuncAttributeMaxDynamicSharedMemorySize,
                         (int)sizeof(Smem));
    ntm_kernel<<<128, NT, sizeof(Smem)>>>(
        (const float*)d_in[0],   // x
        (const float*)d_in[1],   // Wc
        (const float*)d_in[2],   // bc
        (const float*)d_in[3],   // Wr
        (const float*)d_in[4],   // br
        (const float*)d_in[5],   // Ww
        (const float*)d_in[6],   // bw
        (const float*)d_in[7],   // Wf
        (const float*)d_in[8],   // bf
        (const float*)d_in[9],   // r_bias
        (const float*)d_in[10],  // w_bias
        (const float*)d_in[11],  // M_bias
        (float*)d_out);
}